// round 15
// baseline (speedup 1.0000x reference)
#include <cuda_runtime.h>
#include <cuda_fp16.h>
#include <math.h>
#include <stdint.h>

// Problem constants
#define Bn   4
#define Sn   4096
#define Dn   1024
#define Mn   128
#define Cn   128
#define NCn  (Sn / Cn)
#define BSn  (Bn * Sn)
#define DECAYF 0.99f
#define LRF    0.01f

// Scratch (device globals)
__device__ __half g_kh[BSn * Mn], g_kl[BSn * Mn];
__device__ __half g_vh[BSn * Mn], g_vl[BSn * Mn];
__device__ __half g_qh[BSn * Mn], g_ql[BSn * Mn];
__device__ float  g_att[BSn * Mn];               // intra part only
__device__ float  g_dS [Bn * NCn * Mn * Mn];
__device__ __half g_S16[Bn * NCn * Mn * Mn];
__device__ __half g_W16[4 * 128 * 1024];         // Wk|Wv|Wq|Wo as f16

// ===========================================================================
// helpers
// ===========================================================================
__device__ __forceinline__ uint32_t smem_u32(const void* p) {
    uint32_t a;
    asm("{ .reg .u64 t; cvta.to.shared.u64 t, %1; cvt.u32.u64 %0, t; }"
        : "=r"(a) : "l"(p));
    return a;
}
__device__ __forceinline__ void splith(float v, __half& h, __half& l) {
    h = __float2half_rn(v);
    l = __float2half_rn(v - __half2float(h));
}
__device__ __forceinline__ uint32_t packh2(__half a, __half b) {
    __half2 t = __halves2half2(a, b);
    return *(uint32_t*)&t;
}
__device__ __forceinline__ void mma_f16(float* d, const uint32_t* a, const uint32_t* b) {
    asm volatile(
        "mma.sync.aligned.m16n8k16.row.col.f32.f16.f16.f32 "
        "{%0,%1,%2,%3}, {%4,%5,%6,%7}, {%8,%9}, {%0,%1,%2,%3};"
        : "+f"(d[0]), "+f"(d[1]), "+f"(d[2]), "+f"(d[3])
        : "r"(a[0]), "r"(a[1]), "r"(a[2]), "r"(a[3]), "r"(b[0]), "r"(b[1]));
}
__device__ __forceinline__ void ldsm_x4(uint32_t* r, uint32_t addr) {
    asm volatile("ldmatrix.sync.aligned.m8n8.x4.shared.b16 {%0,%1,%2,%3}, [%4];"
        : "=r"(r[0]), "=r"(r[1]), "=r"(r[2]), "=r"(r[3]) : "r"(addr));
}
__device__ __forceinline__ void ldsm_x2(uint32_t* r, uint32_t addr) {
    asm volatile("ldmatrix.sync.aligned.m8n8.x2.shared.b16 {%0,%1}, [%2];"
        : "=r"(r[0]), "=r"(r[1]) : "r"(addr));
}
#define CPASYNC16(sa, gp) \
    asm volatile("cp.async.ca.shared.global [%0], [%1], 16;" :: "r"(sa), "l"(gp))
#define CPCOMMIT() asm volatile("cp.async.commit_group;")
#define CPWAIT2()  asm volatile("cp.async.wait_group 2;")
#define CPWAIT1()  asm volatile("cp.async.wait_group 1;")
#define CPWAIT0()  asm volatile("cp.async.wait_group 0;")

// ldmatrix lane-role offsets:
//   A x4 tiles: rows (l&7)+((l>>3)&1)*8, k-half (l>>4)*8
//   B x2 tiles: rows (l&7), k-half ((l>>3)&1)*8
#define AROW_F(l) (((l) & 7) + (((l) >> 3) & 1) * 8)
#define ACOL_F(l) (((l) >> 4) * 8)
#define BROW_F(l) ((l) & 7)
#define BCOL_F(l) ((((l) >> 3) & 1) * 8)

extern __shared__ float sm_dyn[];

// ===========================================================================
// conv_w: weights -> f16
// ===========================================================================
__global__ void __launch_bounds__(256) conv_w_kernel(
    const float* __restrict__ Wk, const float* __restrict__ Wv,
    const float* __restrict__ Wq, const float* __restrict__ Wo)
{
    const int i = blockIdx.x * 256 + threadIdx.x;   // < 524288
    float v;
    if (i < 131072)       v = Wk[i];
    else if (i < 262144)  v = Wv[i - 131072];
    else if (i < 393216)  v = Wq[i - 262144];
    else                  v = Wo[i - 393216];
    g_W16[i] = __float2half_rn(v);
}

// ===========================================================================
// K1 proj: 64-row tiles (tail-balanced). grid (256, 3), 2 CTAs/SM.
// A fp32 reg-prefetch + cvt at staging (64x16/chunk), B f16 cp.async 4-ring.
// 8 warps 2x4, warp tile 32x32, ldmatrix fragments.
// smem: sA[2][1536] + sB[4][3072] halves = 30720 B.
// ===========================================================================
#define SROWH 24
#define STGH  3072
#define PSTA  1536     // 64 rows x 24 halves

__global__ void __launch_bounds__(256, 2) proj_kernel(
    const float* __restrict__ x,
    const float* __restrict__ bk, const float* __restrict__ bv,
    const float* __restrict__ bq)
{
    __half* sA = (__half*)sm_dyn;
    __half* sB = sA + 2 * PSTA;
    const uint32_t uA = smem_u32(sA);
    const uint32_t uB = smem_u32(sB);

    const int tid = threadIdx.x;
    const int lane = tid & 31, wid = tid >> 5;
    const int wm = wid >> 2, wn = wid & 3;          // 2 x 4 warps
    const int g = lane >> 2, t4 = lane & 3;
    const int brow = tid >> 1, bhalf = tid & 1;     // B staging role
    const int arow = tid >> 2, ac4 = (tid & 3) * 4; // A staging role

    const size_t rb = (size_t)blockIdx.x * 64;
    const int yv = blockIdx.y;
    const float* bias = (yv == 0) ? bk : (yv == 1) ? bv : bq;
    __half* Ch = ((yv == 0) ? g_kh : (yv == 1) ? g_vh : g_qh) + rb * Mn;
    __half* Cl = ((yv == 0) ? g_kl : (yv == 1) ? g_vl : g_ql) + rb * Mn;
    const float* A = x + rb * Dn;
    const __half* Bm = g_W16 + (size_t)yv * 131072;

    const uint32_t aoff0 = ((wm * 32 + AROW_F(lane)) * SROWH + ACOL_F(lane)) * 2;
    const uint32_t aoff1 = aoff0 + 16 * SROWH * 2;
    const uint32_t boff  = ((wn * 32 + BROW_F(lane)) * SROWH + BCOL_F(lane)) * 2;

    float acc[2][4][4];
#pragma unroll
    for (int mt = 0; mt < 2; mt++)
#pragma unroll
        for (int nt = 0; nt < 4; nt++)
#pragma unroll
            for (int r = 0; r < 4; r++) acc[mt][nt][r] = 0.f;

#define ISSUE_B(ch) do { \
    const uint32_t _d = (((ch) & 3) * STGH + brow * SROWH + bhalf * 8) * 2; \
    CPASYNC16(uB + _d, Bm + (size_t)brow * Dn + (ch) * 16 + bhalf * 8); \
} while (0)

    ISSUE_B(0); CPCOMMIT();
    ISSUE_B(1); CPCOMMIT();
    ISSUE_B(2); CPCOMMIT();

    float4 pre = *(const float4*)(A + (size_t)arow * Dn + ac4);

    for (int ch = 0; ch < 64; ch++) {
        {
            __half2 h0 = __floats2half2_rn(pre.x, pre.y);
            __half2 h1 = __floats2half2_rn(pre.z, pre.w);
            uint32_t w[2] = { *(uint32_t*)&h0, *(uint32_t*)&h1 };
            *(uint2*)(sA + (ch & 1) * PSTA + arow * SROWH + ac4) = *(uint2*)w;
        }
        if (ch + 1 < 64)
            pre = *(const float4*)(A + (size_t)arow * Dn + (ch + 1) * 16 + ac4);
        CPWAIT2();
        __syncthreads();
        if (ch + 3 < 64) ISSUE_B(ch + 3);
        CPCOMMIT();

        const uint32_t aB = uA + ((ch & 1) * PSTA) * 2;
        const uint32_t bB = uB + ((ch & 3) * STGH) * 2 + boff;

        uint32_t af[2][4];
        ldsm_x4(af[0], aB + aoff0);
        ldsm_x4(af[1], aB + aoff1);
#pragma unroll
        for (int nt = 0; nt < 4; nt++) {
            uint32_t bf[2];
            ldsm_x2(bf, bB + nt * (8 * SROWH * 2));
            mma_f16(acc[0][nt], af[0], bf);
            mma_f16(acc[1][nt], af[1], bf);
        }
    }
#undef ISSUE_B

#pragma unroll
    for (int mt = 0; mt < 2; mt++) {
        const int r0 = wm * 32 + mt * 16 + g;
#pragma unroll
        for (int nt = 0; nt < 4; nt++) {
            const int c0 = wn * 32 + nt * 8 + 2 * t4;
            const float b0 = bias[c0], b1 = bias[c0 + 1];
            float v00 = acc[mt][nt][0] + b0, v01 = acc[mt][nt][1] + b1;
            float v10 = acc[mt][nt][2] + b0, v11 = acc[mt][nt][3] + b1;
            __half h0,l0,h1,l1;
            splith(v00, h0, l0); splith(v01, h1, l1);
            *(uint32_t*)(Ch + (size_t)r0 * Mn + c0) = packh2(h0, h1);
            *(uint32_t*)(Cl + (size_t)r0 * Mn + c0) = packh2(l0, l1);
            splith(v10, h0, l0); splith(v11, h1, l1);
            *(uint32_t*)(Ch + (size_t)(r0 + 8) * Mn + c0) = packh2(h0, h1);
            *(uint32_t*)(Cl + (size_t)(r0 + 8) * Mn + c0) = packh2(l0, l1);
        }
    }
}

// ===========================================================================
// K4+K5 fused: stage 1 inter GEMM, stage 2 y = att x Wo^T (2-deep tile ring)
// smem: ring 8*3072 halves + sAtt 128*136 + sW 2x128*136 = 153600 B
// ===========================================================================
#define AP 136
#define APL (128 * AP)

__global__ void __launch_bounds__(256) fuse_out_kernel(
    const float* __restrict__ bo, float* __restrict__ y)
{
    __half* sQ   = (__half*)sm_dyn;        // stage-1 A ring (4)
    __half* sS   = sQ + 4 * STGH;          // stage-1 B ring (4)
    __half* sAtt = sQ + 8 * STGH;          // 128 x AP
    __half* sW   = sAtt + APL;             // 2 x 128 x AP
    const uint32_t uQ = smem_u32(sQ), uS = smem_u32(sS);
    const uint32_t uAtt = smem_u32(sAtt), uW = smem_u32(sW);
    const int tid = threadIdx.x;
    const int lane = tid & 31, wid = tid >> 5;
    const int wm = wid >> 1, wn = wid & 1;
    const int g = lane >> 2, t4 = lane & 3;
    const int row = tid >> 1, half = tid & 1;

    const uint32_t aoffS0 = ((wm * 32 + AROW_F(lane)) * SROWH + ACOL_F(lane)) * 2;
    const uint32_t aoffS1 = aoffS0 + 16 * SROWH * 2;
    const uint32_t boffS  = ((wn * 64 + BROW_F(lane)) * SROWH + BCOL_F(lane)) * 2;
    const uint32_t aoffA0 = ((wm * 32 + AROW_F(lane)) * AP + ACOL_F(lane)) * 2;
    const uint32_t aoffA1 = aoffA0 + 16 * AP * 2;
    const uint32_t boffA  = ((wn * 64 + BROW_F(lane)) * AP + BCOL_F(lane)) * 2;

    const int b = blockIdx.x / NCn;
    const int c = blockIdx.x % NCn;
    const size_t base  = ((size_t)b * Sn + (size_t)c * Cn) * Mn;
    const size_t sbase = ((size_t)b * NCn + c) * 16384;
    const __half* Aq = g_qh + base;
    const __half* Bs = g_S16 + sbase;
    const __half* Wo = g_W16 + 393216;

    // ---------------- stage 1: inter GEMM ----------------
    float acc[2][8][4];
#pragma unroll
    for (int mt = 0; mt < 2; mt++)
#pragma unroll
        for (int nt = 0; nt < 8; nt++)
#pragma unroll
            for (int r = 0; r < 4; r++) acc[mt][nt][r] = 0.f;

#define ISSUE1(ch) do { \
    const uint32_t _d = (((ch) & 3) * STGH + row * SROWH + half * 8) * 2; \
    const size_t _s = (size_t)row * Mn + (ch) * 16 + half * 8; \
    CPASYNC16(uQ + _d, Aq + _s); \
    CPASYNC16(uS + _d, Bs + _s); \
} while (0)

    ISSUE1(0); CPCOMMIT();
    ISSUE1(1); CPCOMMIT();
    ISSUE1(2); CPCOMMIT();

    for (int ch = 0; ch < 8; ch++) {
        CPWAIT2();
        __syncthreads();
        if (ch + 3 < 8) ISSUE1(ch + 3);
        CPCOMMIT();

        const uint32_t aB = uQ + ((ch & 3) * STGH) * 2;
        const uint32_t bB = uS + ((ch & 3) * STGH) * 2 + boffS;

        uint32_t af[2][4];
        ldsm_x4(af[0], aB + aoffS0);
        ldsm_x4(af[1], aB + aoffS1);
#pragma unroll
        for (int nt = 0; nt < 8; nt++) {
            uint32_t bf[2];
            ldsm_x2(bf, bB + nt * (8 * SROWH * 2));
            mma_f16(acc[0][nt], af[0], bf);
            mma_f16(acc[1][nt], af[1], bf);
        }
    }
#undef ISSUE1

    CPWAIT0();
    __syncthreads();

    // epilogue: att = intra (fp32) + decay^t * inter -> fp16 tile
#pragma unroll
    for (int mt = 0; mt < 2; mt++) {
        const int r0 = wm * 32 + mt * 16 + g;
        const float f0 = powf(DECAYF, (float)r0);
        const float f1 = powf(DECAYF, (float)(r0 + 8));
#pragma unroll
        for (int nt = 0; nt < 8; nt++) {
            const int c0 = wn * 64 + nt * 8 + 2 * t4;
            float2 i0v = *(const float2*)(g_att + base + (size_t)r0 * Mn + c0);
            float2 i1v = *(const float2*)(g_att + base + (size_t)(r0 + 8) * Mn + c0);
            __half2 h0 = __floats2half2_rn(i0v.x + f0 * acc[mt][nt][0],
                                           i0v.y + f0 * acc[mt][nt][1]);
            __half2 h1 = __floats2half2_rn(i1v.x + f1 * acc[mt][nt][2],
                                           i1v.y + f1 * acc[mt][nt][3]);
            *(uint32_t*)(sAtt + r0 * AP + c0)       = *(uint32_t*)&h0;
            *(uint32_t*)(sAtt + (r0 + 8) * AP + c0) = *(uint32_t*)&h1;
        }
    }

#define ISSUE_TILE(cb) do { \
    const uint32_t _bo = ((cb) & 1) * APL; \
    _Pragma("unroll") \
    for (int _it = 0; _it < 8; _it++) { \
        const int _sid = tid + _it * 256; \
        const int _u = _sid >> 4, _sg = _sid & 15; \
        CPASYNC16(uW + (_bo + _u * AP + _sg * 8) * 2, \
                  Wo + (size_t)((cb) * 128 + _u) * Mn + _sg * 8); \
    } \
} while (0)

    ISSUE_TILE(0); CPCOMMIT();
    ISSUE_TILE(1); CPCOMMIT();
    __syncthreads();   // sAtt visible to all warps

    // ---------------- stage 2: y = att x Wo^T + bo ----------------
    const size_t yrow = (size_t)b * Sn + (size_t)c * Cn;

    for (int cb = 0; cb < 8; cb++) {
        CPWAIT1();
        __syncthreads();
        const uint32_t wB = uW + ((cb & 1) * APL) * 2 + boffA;

        float acy[2][8][4];
#pragma unroll
        for (int mt = 0; mt < 2; mt++)
#pragma unroll
            for (int nt = 0; nt < 8; nt++)
#pragma unroll
                for (int r = 0; r < 4; r++) acy[mt][nt][r] = 0.f;

#pragma unroll
        for (int kc = 0; kc < 8; kc++) {
            const uint32_t ko2 = kc * 16 * 2;
            uint32_t af[2][4];
            ldsm_x4(af[0], uAtt + aoffA0 + ko2);
            ldsm_x4(af[1], uAtt + aoffA1 + ko2);
#pragma unroll
            for (int nt = 0; nt < 8; nt++) {
                uint32_t bf[2];
                ldsm_x2(bf, wB + nt * (8 * AP * 2) + ko2);
                mma_f16(acy[0][nt], af[0], bf);
                mma_f16(acy[1][nt], af[1], bf);
            }
        }

#pragma unroll
        for (int mt = 0; mt < 2; mt++) {
            const int r0 = wm * 32 + mt * 16 + g;
#pragma unroll
            for (int nt = 0; nt < 8; nt++) {
                const int c0 = wn * 64 + nt * 8 + 2 * t4;
                const float b0 = bo[cb * 128 + c0], b1 = bo[cb * 128 + c0 + 1];
                *(float2*)(y + (yrow + r0) * Dn + cb * 128 + c0) =
                    make_float2(acy[mt][nt][0] + b0, acy[mt][nt][1] + b1);
                *(float2*)(y + (yrow + r0 + 8) * Dn + cb * 128 + c0) =
                    make_float2(acy[mt][nt][2] + b0, acy[mt][nt][3] + b1);
            }
        }
        __syncthreads();
        if (cb + 2 < 8) { ISSUE_TILE(cb + 2); }
        CPCOMMIT();
    }
#undef ISSUE_TILE
}

// ===========================================================================
// K2: chunk — fp16 hi/lo 2-plane compensated, three 128^3 GEMMs on resident
// smem planes, ldmatrix fragments. grid 128, 256 thr. smem ~209.4 KB.
// ===========================================================================
#define CP 136
#define CPL (128 * CP)

__device__ __forceinline__ void gemm_sm_f16(
    const __half* __restrict__ Ah, const __half* __restrict__ Al,
    const __half* __restrict__ Bh, const __half* __restrict__ Bl,
    float acc[2][8][4], int wm, int wn, int lane)
{
    const uint32_t uAh = smem_u32(Ah), uAl = smem_u32(Al);
    const uint32_t uBh = smem_u32(Bh), uBl = smem_u32(Bl);
    const uint32_t aoff0 = ((wm * 32 + AROW_F(lane)) * CP + ACOL_F(lane)) * 2;
    const uint32_t aoff1 = aoff0 + 16 * CP * 2;
    const uint32_t boff  = ((wn * 64 + BROW_F(lane)) * CP + BCOL_F(lane)) * 2;

#pragma unroll
    for (int kk = 0; kk < 8; kk++) {
        const uint32_t ko2 = kk * 16 * 2;
        uint32_t ah[2][4], al[2][4];
        ldsm_x4(ah[0], uAh + aoff0 + ko2);
        ldsm_x4(ah[1], uAh + aoff1 + ko2);
        ldsm_x4(al[0], uAl + aoff0 + ko2);
        ldsm_x4(al[1], uAl + aoff1 + ko2);
#pragma unroll
        for (int nt = 0; nt < 8; nt++) {
            const uint32_t bo2 = boff + nt * (8 * CP * 2) + ko2;
            uint32_t bh[2], bl[2];
            ldsm_x2(bh, uBh + bo2);
            ldsm_x2(bl, uBl + bo2);
#pragma unroll
            for (int mt = 0; mt < 2; mt++) {
                mma_f16(acc[mt][nt], ah[mt], bh);
                mma_f16(acc[mt][nt], al[mt], bh);
                mma_f16(acc[mt][nt], ah[mt], bl);
            }
        }
    }
}

__global__ void __launch_bounds__(256) chunk_kernel()
{
    __half* Qh  = (__half*)sm_dyn;      // -> S planes -> Ktw planes
    __half* Ql  = Qh + CPL;
    __half* Kh  = Qh + 2 * CPL;
    __half* Kl  = Qh + 3 * CPL;
    __half* Vth = Qh + 4 * CPL;
    __half* Vtl = Qh + 5 * CPL;
    float* dpow = (float*)(Qh + 6 * CPL);

    const uint32_t uQh = smem_u32(Qh);
    const int tid = threadIdx.x;
    const int lane = tid & 31, wid = tid >> 5;
    const int wm = wid >> 1, wn = wid & 1;
    const int g = lane >> 2, t4 = lane & 3;
    const int b = blockIdx.x / NCn;
    const int c = blockIdx.x % NCn;
    const size_t base = ((size_t)b * Sn + (size_t)c * Cn) * Mn;

#pragma unroll
    for (int it = 0; it < 8; it++) {
        const int sid = tid + it * 256;
        const int u = sid >> 4, seg = sid & 15;
        const uint32_t dof = (u * CP + seg * 8) * 2;
        const size_t sof = base + (size_t)u * Mn + seg * 8;
        CPASYNC16(uQh + dof,               g_qh + sof);
        CPASYNC16(uQh + CPL * 2 + dof,     g_ql + sof);
        CPASYNC16(uQh + 2 * CPL * 2 + dof, g_kh + sof);
        CPASYNC16(uQh + 3 * CPL * 2 + dof, g_kl + sof);
    }
    CPCOMMIT();

    if (tid < 128) dpow[tid] = powf(DECAYF, (float)tid);

#pragma unroll
    for (int it = 0; it < 8; it++) {
        const int task = tid + it * 256;
        const int u = task & 127, i0 = (task >> 7) * 8;
        uint4 dh = *(const uint4*)(g_vh + base + (size_t)u * Mn + i0);
        uint4 dl = *(const uint4*)(g_vl + base + (size_t)u * Mn + i0);
        const __half* ph = (const __half*)&dh;
        const __half* pl = (const __half*)&dl;
#pragma unroll
        for (int j = 0; j < 8; j++) {
            Vth[(i0 + j) * CP + u] = ph[j];
            Vtl[(i0 + j) * CP + u] = pl[j];
        }
    }

    CPWAIT0();
    __syncthreads();

    float acc[2][8][4];
#pragma unroll
    for (int mt = 0; mt < 2; mt++)
#pragma unroll
        for (int nt = 0; nt < 8; nt++)
#pragma unroll
            for (int r = 0; r < 4; r++) acc[mt][nt][r] = 0.f;
    gemm_sm_f16(Qh, Ql, Kh, Kl, acc, wm, wn, lane);

#pragma unroll
    for (int mt = 0; mt < 2; mt++)
#pragma unroll
        for (int nt = 0; nt < 8; nt++)
#pragma unroll
            for (int r = 0; r < 4; r++) {
                const int t = wm * 32 + mt * 16 + g + ((r >= 2) ? 8 : 0);
                const int u = wn * 64 + nt * 8 + 2 * t4 + (r & 1);
                acc[mt][nt][r] = (u < t) ? acc[mt][nt][r] * (LRF * dpow[t - 1 - u]) : 0.f;
            }
    __syncthreads();

#pragma unroll
    for (int mt = 0; mt < 2; mt++) {
        const int r0 = wm * 32 + mt * 16 + g;
#pragma unroll
        for (int nt = 0; nt < 8; nt++) {
            const int c0 = wn * 64 + nt * 8 + 2 * t4;
            __half h0,l0,h1,l1;
            splith(acc[mt][nt][0], h0, l0); splith(acc[mt][nt][1], h1, l1);
            *(uint32_t*)(Qh + r0 * CP + c0) = packh2(h0, h1);
            *(uint32_t*)(Ql + r0 * CP + c0) = packh2(l0, l1);
            splith(acc[mt][nt][2], h0, l0); splith(acc[mt][nt][3], h1, l1);
            *(uint32_t*)(Qh + (r0 + 8) * CP + c0) = packh2(h0, h1);
            *(uint32_t*)(Ql + (r0 + 8) * CP + c0) = packh2(l0, l1);
        }
    }
    __syncthreads();

    float acc2[2][8][4];
#pragma unroll
    for (int mt = 0; mt < 2; mt++)
#pragma unroll
        for (int nt = 0; nt < 8; nt++)
#pragma unroll
            for (int r = 0; r < 4; r++) acc2[mt][nt][r] = 0.f;
    gemm_sm_f16(Qh, Ql, Vth, Vtl, acc2, wm, wn, lane);
#pragma unroll
    for (int mt = 0; mt < 2; mt++) {
        const int r0 = wm * 32 + mt * 16 + g;
#pragma unroll
        for (int nt = 0; nt < 8; nt++) {
            const int c0 = wn * 64 + nt * 8 + 2 * t4;
            *(float2*)(g_att + base + (size_t)r0 * Mn + c0)       = make_float2(acc2[mt][nt][0], acc2[mt][nt][1]);
            *(float2*)(g_att + base + (size_t)(r0 + 8) * Mn + c0) = make_float2(acc2[mt][nt][2], acc2[mt][nt][3]);
        }
    }
    __syncthreads();

#pragma unroll
    for (int it = 0; it < 8; it++) {
        const int task = tid + it * 256;
        const int u = task & 127, j0 = (task >> 7) * 8;
        const float w = LRF * dpow[127 - u];
#pragma unroll
        for (int j = 0; j < 8; j++) {
            float f = (__half2float(Kh[u * CP + j0 + j]) +
                       __half2float(Kl[u * CP + j0 + j])) * w;
            __half h, l; splith(f, h, l);
            Qh[(j0 + j) * CP + u] = h;
            Ql[(j0 + j) * CP + u] = l;
        }
    }
    __syncthreads();

    float acc3[2][8][4];
#pragma unroll
    for (int mt = 0; mt < 2; mt++)
#pragma unroll
        for (int nt = 0; nt < 8; nt++)
#pragma unroll
            for (int r = 0; r < 4; r++) acc3[mt][nt][r] = 0.f;
    gemm_sm_f16(Vth, Vtl, Qh, Ql, acc3, wm, wn, lane);

    const size_t dsbase = ((size_t)b * NCn + c) * (Mn * Mn);
#pragma unroll
    for (int mt = 0; mt < 2; mt++) {
        const int r0 = wm * 32 + mt * 16 + g;
#pragma unroll
        for (int nt = 0; nt < 8; nt++) {
            const int c0 = wn * 64 + nt * 8 + 2 * t4;
            *(float2*)(g_dS + dsbase + (size_t)r0 * Mn + c0)       = make_float2(acc3[mt][nt][0], acc3[mt][nt][1]);
            *(float2*)(g_dS + dsbase + (size_t)(r0 + 8) * Mn + c0) = make_float2(acc3[mt][nt][2], acc3[mt][nt][3]);
        }
    }
}

// ===========================================================================
// K3: tile-parallel two-level scan (R10 winner)
// ===========================================================================
__global__ void __launch_bounds__(256) scan_kernel(float* __restrict__ state_out)
{
    __shared__ float t[32][64];
    __shared__ float seg[4][64];
    __shared__ float carr[4][64];

    const int tid = threadIdx.x;
    const int b   = blockIdx.x >> 8;
    const int ij0 = (blockIdx.x & 255) * 64;
    const float dc  = powf(DECAYF, (float)Cn);
    const float dc8 = powf(dc, 8.0f);

#pragma unroll
    for (int it = 0; it < 8; it++) {
        const int idx = tid + it * 256;
        const int cc = idx >> 6, j = idx & 63;
        t[cc][j] = g_dS[((size_t)b * NCn + cc) * 16384 + ij0 + j];
    }
    __syncthreads();

    const int q = tid >> 6, j = tid & 63;

    {
        float r = 0.f;
#pragma unroll
        for (int i = 0; i < 8; i++) r = dc * r + t[q * 8 + i][j];
        seg[q][j] = r;
    }
    __syncthreads();

    if (tid < 64) {
        float csum = 0.f;
#pragma unroll
        for (int qq = 0; qq < 4; qq++) {
            carr[qq][tid] = csum;
            csum = dc8 * csum + seg[qq][tid];
        }
        state_out[(size_t)b * 16384 + ij0 + tid] = csum;
    }
    __syncthreads();

    {
        float r = carr[q][j];
#pragma unroll
        for (int i = 0; i < 8; i++) {
            const int cc = q * 8 + i;
            g_S16[((size_t)b * NCn + cc) * 16384 + ij0 + j] = __float2half_rn(r);
            r = dc * r + t[cc][j];
        }
    }
}

// ===========================================================================
extern "C" void kernel_launch(void* const* d_in, const int* in_sizes, int n_in,
                              void* d_out, int out_size)
{
    const float* x  = (const float*)d_in[0];
    const float* Wk = (const float*)d_in[1];
    const float* bk = (const float*)d_in[2];
    const float* Wv = (const float*)d_in[3];
    const float* bv = (const float*)d_in[4];
    const float* Wq = (const float*)d_in[5];
    const float* bq = (const float*)d_in[6];
    const float* Wo = (const float*)d_in[7];
    const float* bo = (const float*)d_in[8];

    float* y         = (float*)d_out;
    float* state_out = y + (size_t)BSn * Dn;

    const int PROJ_SMEM  = (2 * PSTA + 4 * STGH) * 2;         // 30720
    const int FUSE_SMEM  = (8 * STGH + 3 * APL) * 2;          // 153600
    const int CHUNK_SMEM = 6 * CPL * 2 + 512;                 // 209408

    cudaFuncSetAttribute(proj_kernel,     cudaFuncAttributeMaxDynamicSharedMemorySize, PROJ_SMEM);
    cudaFuncSetAttribute(fuse_out_kernel, cudaFuncAttributeMaxDynamicSharedMemorySize, FUSE_SMEM);
    cudaFuncSetAttribute(chunk_kernel,    cudaFuncAttributeMaxDynamicSharedMemorySize, CHUNK_SMEM);

    conv_w_kernel<<<2048, 256>>>(Wk, Wv, Wq, Wo);
    proj_kernel<<<dim3(BSn / 64, 3), 256, PROJ_SMEM>>>(x, bk, bv, bq);
    chunk_kernel<<<Bn * NCn, 256, CHUNK_SMEM>>>();
    scan_kernel<<<Bn * 256, 256>>>(state_out);
    fuse_out_kernel<<<Bn * NCn, 256, FUSE_SMEM>>>(bo, y);
}

// round 16
// speedup vs baseline: 1.1419x; 1.1419x over previous
#include <cuda_runtime.h>
#include <cuda_fp16.h>
#include <math.h>
#include <stdint.h>

// Problem constants
#define Bn   4
#define Sn   4096
#define Dn   1024
#define Mn   128
#define Cn   128
#define NCn  (Sn / Cn)
#define BSn  (Bn * Sn)
#define DECAYF 0.99f
#define LRF    0.01f

// Scratch (device globals)
__device__ __half g_kh[BSn * Mn], g_kl[BSn * Mn];
__device__ __half g_vh[BSn * Mn], g_vl[BSn * Mn];
__device__ __half g_qh[BSn * Mn], g_ql[BSn * Mn];
__device__ float  g_att[BSn * Mn];               // intra part only
__device__ float  g_dS [Bn * NCn * Mn * Mn];
__device__ __half g_S16[Bn * NCn * Mn * Mn];
__device__ __half g_W16[4 * 128 * 1024];         // Wk|Wv|Wq|Wo as f16

// ===========================================================================
// helpers
// ===========================================================================
__device__ __forceinline__ uint32_t smem_u32(const void* p) {
    uint32_t a;
    asm("{ .reg .u64 t; cvta.to.shared.u64 t, %1; cvt.u32.u64 %0, t; }"
        : "=r"(a) : "l"(p));
    return a;
}
__device__ __forceinline__ void splith(float v, __half& h, __half& l) {
    h = __float2half_rn(v);
    l = __float2half_rn(v - __half2float(h));
}
__device__ __forceinline__ uint32_t packh2(__half a, __half b) {
    __half2 t = __halves2half2(a, b);
    return *(uint32_t*)&t;
}
__device__ __forceinline__ void mma_f16(float* d, const uint32_t* a, const uint32_t* b) {
    asm volatile(
        "mma.sync.aligned.m16n8k16.row.col.f32.f16.f16.f32 "
        "{%0,%1,%2,%3}, {%4,%5,%6,%7}, {%8,%9}, {%0,%1,%2,%3};"
        : "+f"(d[0]), "+f"(d[1]), "+f"(d[2]), "+f"(d[3])
        : "r"(a[0]), "r"(a[1]), "r"(a[2]), "r"(a[3]), "r"(b[0]), "r"(b[1]));
}
__device__ __forceinline__ void ldsm_x4(uint32_t* r, uint32_t addr) {
    asm volatile("ldmatrix.sync.aligned.m8n8.x4.shared.b16 {%0,%1,%2,%3}, [%4];"
        : "=r"(r[0]), "=r"(r[1]), "=r"(r[2]), "=r"(r[3]) : "r"(addr));
}
__device__ __forceinline__ void ldsm_x2(uint32_t* r, uint32_t addr) {
    asm volatile("ldmatrix.sync.aligned.m8n8.x2.shared.b16 {%0,%1}, [%2];"
        : "=r"(r[0]), "=r"(r[1]) : "r"(addr));
}
#define CPASYNC16(sa, gp) \
    asm volatile("cp.async.ca.shared.global [%0], [%1], 16;" :: "r"(sa), "l"(gp))
#define CPCOMMIT() asm volatile("cp.async.commit_group;")
#define CPWAIT2()  asm volatile("cp.async.wait_group 2;")
#define CPWAIT1()  asm volatile("cp.async.wait_group 1;")
#define CPWAIT0()  asm volatile("cp.async.wait_group 0;")

// ldmatrix lane-role offsets:
//   A x4 tiles: rows (l&7)+((l>>3)&1)*8, k-half (l>>4)*8
//   B x2 tiles: rows (l&7), k-half ((l>>3)&1)*8
#define AROW_F(l) (((l) & 7) + (((l) >> 3) & 1) * 8)
#define ACOL_F(l) (((l) >> 4) * 8)
#define BROW_F(l) ((l) & 7)
#define BCOL_F(l) ((((l) >> 3) & 1) * 8)

extern __shared__ float sm_dyn[];

// ===========================================================================
// conv_w: weights -> f16
// ===========================================================================
__global__ void __launch_bounds__(256) conv_w_kernel(
    const float* __restrict__ Wk, const float* __restrict__ Wv,
    const float* __restrict__ Wq, const float* __restrict__ Wo)
{
    const int i = blockIdx.x * 256 + threadIdx.x;   // < 524288
    float v;
    if (i < 131072)       v = Wk[i];
    else if (i < 262144)  v = Wv[i - 131072];
    else if (i < 393216)  v = Wq[i - 262144];
    else                  v = Wo[i - 393216];
    g_W16[i] = __float2half_rn(v);
}

// ===========================================================================
// GEMM A-fp32 (proj): A fp32 reg-prefetch + cvt at staging, B f16 cp.async.
// 256 thr, 8 warps 4x2, warp tile 32x64, K-chunk 16. ldmatrix fragments.
// smem: sA[2][3072] + sB[4][3072] halves = 36864 B.
// ===========================================================================
#define SROWH 24
#define STGH  3072

__device__ __forceinline__ void gemm_proj(
    const float* __restrict__ A, int lda,
    const __half* __restrict__ Bm, int ldb, int K,
    const float* __restrict__ bias,
    __half* __restrict__ Ch, __half* __restrict__ Cl, int ldc)
{
    __half* sA = (__half*)sm_dyn;
    __half* sB = sA + 2 * STGH;
    const uint32_t uA = smem_u32(sA);
    const uint32_t uB = smem_u32(sB);
    const int tid = threadIdx.x;
    const int lane = tid & 31, wid = tid >> 5;
    const int wm = wid >> 1, wn = wid & 1;
    const int g = lane >> 2, t4 = lane & 3;
    const int row = tid >> 1, half = tid & 1;

    const uint32_t aoff0 = ((wm * 32 + AROW_F(lane)) * SROWH + ACOL_F(lane)) * 2;
    const uint32_t aoff1 = aoff0 + 16 * SROWH * 2;
    const uint32_t boff  = ((wn * 64 + BROW_F(lane)) * SROWH + BCOL_F(lane)) * 2;

    float acc[2][8][4];
#pragma unroll
    for (int mt = 0; mt < 2; mt++)
#pragma unroll
        for (int nt = 0; nt < 8; nt++)
#pragma unroll
            for (int r = 0; r < 4; r++) acc[mt][nt][r] = 0.f;

    const int nc = K >> 4;

#define ISSUE_B(ch) do { \
    const uint32_t _d = (((ch) & 3) * STGH + row * SROWH + half * 8) * 2; \
    CPASYNC16(uB + _d, Bm + (size_t)row * ldb + (ch) * 16 + half * 8); \
} while (0)

    ISSUE_B(0); CPCOMMIT();
    ISSUE_B(1); CPCOMMIT();
    ISSUE_B(2); CPCOMMIT();

    float pre[8];
    {
        const float* ap = A + (size_t)row * lda + half * 8;
        float4 a0 = *(const float4*)ap, a1 = *(const float4*)(ap + 4);
        pre[0]=a0.x; pre[1]=a0.y; pre[2]=a0.z; pre[3]=a0.w;
        pre[4]=a1.x; pre[5]=a1.y; pre[6]=a1.z; pre[7]=a1.w;
    }

    for (int ch = 0; ch < nc; ch++) {
        {
            uint32_t w[4];
#pragma unroll
            for (int j = 0; j < 4; j++) {
                __half2 h = __floats2half2_rn(pre[2*j], pre[2*j+1]);
                w[j] = *(uint32_t*)&h;
            }
            *(uint4*)(sA + (ch & 1) * STGH + row * SROWH + half * 8) = *(uint4*)w;
        }
        if (ch + 1 < nc) {
            const float* ap = A + (size_t)row * lda + (ch + 1) * 16 + half * 8;
            float4 a0 = *(const float4*)ap, a1 = *(const float4*)(ap + 4);
            pre[0]=a0.x; pre[1]=a0.y; pre[2]=a0.z; pre[3]=a0.w;
            pre[4]=a1.x; pre[5]=a1.y; pre[6]=a1.z; pre[7]=a1.w;
        }
        CPWAIT2();
        __syncthreads();
        if (ch + 3 < nc) ISSUE_B(ch + 3);
        CPCOMMIT();

        const uint32_t aB = uA + ((ch & 1) * STGH) * 2;
        const uint32_t bB = uB + ((ch & 3) * STGH) * 2 + boff;

        uint32_t af[2][4];
        ldsm_x4(af[0], aB + aoff0);
        ldsm_x4(af[1], aB + aoff1);
#pragma unroll
        for (int nt = 0; nt < 8; nt++) {
            uint32_t bf[2];
            ldsm_x2(bf, bB + nt * (8 * SROWH * 2));
            mma_f16(acc[0][nt], af[0], bf);
            mma_f16(acc[1][nt], af[1], bf);
        }
    }
#undef ISSUE_B

#pragma unroll
    for (int mt = 0; mt < 2; mt++) {
        const int r0 = wm * 32 + mt * 16 + g;
#pragma unroll
        for (int nt = 0; nt < 8; nt++) {
            const int c0 = wn * 64 + nt * 8 + 2 * t4;
            const float b0 = bias[c0], b1 = bias[c0 + 1];
            float v00 = acc[mt][nt][0] + b0, v01 = acc[mt][nt][1] + b1;
            float v10 = acc[mt][nt][2] + b0, v11 = acc[mt][nt][3] + b1;
            __half h0,l0,h1,l1;
            splith(v00, h0, l0); splith(v01, h1, l1);
            *(uint32_t*)(Ch + (size_t)r0 * ldc + c0) = packh2(h0, h1);
            *(uint32_t*)(Cl + (size_t)r0 * ldc + c0) = packh2(l0, l1);
            splith(v10, h0, l0); splith(v11, h1, l1);
            *(uint32_t*)(Ch + (size_t)(r0 + 8) * ldc + c0) = packh2(h0, h1);
            *(uint32_t*)(Cl + (size_t)(r0 + 8) * ldc + c0) = packh2(l0, l1);
        }
    }
}

// ===========================================================================
// K1: projections -> hi/lo planes   grid (128, 3)
// ===========================================================================
__global__ void __launch_bounds__(256, 2) proj_kernel(
    const float* __restrict__ x,
    const float* __restrict__ bk, const float* __restrict__ bv,
    const float* __restrict__ bq)
{
    const size_t rb = (size_t)blockIdx.x * 128;
    const int yv = blockIdx.y;
    const float* bias = (yv == 0) ? bk : (yv == 1) ? bv : bq;
    __half* Ch = (yv == 0) ? g_kh : (yv == 1) ? g_vh : g_qh;
    __half* Cl = (yv == 0) ? g_kl : (yv == 1) ? g_vl : g_ql;
    gemm_proj(x + rb * Dn, Dn, g_W16 + (size_t)yv * 131072, Dn, Dn,
              bias, Ch + rb * Mn, Cl + rb * Mn, Mn);
}

// ===========================================================================
// K4+K5 fused: stage 1 inter GEMM, stage 2 y = att x Wo^T (2-deep tile ring)
// smem: ring 8*3072 halves + sAtt 128*136 + sW 2x128*136 = 153600 B
// ===========================================================================
#define AP 136
#define APL (128 * AP)

__global__ void __launch_bounds__(256) fuse_out_kernel(
    const float* __restrict__ bo, float* __restrict__ y)
{
    __half* sQ   = (__half*)sm_dyn;        // stage-1 A ring (4)
    __half* sS   = sQ + 4 * STGH;          // stage-1 B ring (4)
    __half* sAtt = sQ + 8 * STGH;          // 128 x AP
    __half* sW   = sAtt + APL;             // 2 x 128 x AP
    const uint32_t uQ = smem_u32(sQ), uS = smem_u32(sS);
    const uint32_t uAtt = smem_u32(sAtt), uW = smem_u32(sW);
    const int tid = threadIdx.x;
    const int lane = tid & 31, wid = tid >> 5;
    const int wm = wid >> 1, wn = wid & 1;
    const int g = lane >> 2, t4 = lane & 3;
    const int row = tid >> 1, half = tid & 1;

    const uint32_t aoffS0 = ((wm * 32 + AROW_F(lane)) * SROWH + ACOL_F(lane)) * 2;
    const uint32_t aoffS1 = aoffS0 + 16 * SROWH * 2;
    const uint32_t boffS  = ((wn * 64 + BROW_F(lane)) * SROWH + BCOL_F(lane)) * 2;
    const uint32_t aoffA0 = ((wm * 32 + AROW_F(lane)) * AP + ACOL_F(lane)) * 2;
    const uint32_t aoffA1 = aoffA0 + 16 * AP * 2;
    const uint32_t boffA  = ((wn * 64 + BROW_F(lane)) * AP + BCOL_F(lane)) * 2;

    const int b = blockIdx.x / NCn;
    const int c = blockIdx.x % NCn;
    const size_t base  = ((size_t)b * Sn + (size_t)c * Cn) * Mn;
    const size_t sbase = ((size_t)b * NCn + c) * 16384;
    const __half* Aq = g_qh + base;
    const __half* Bs = g_S16 + sbase;
    const __half* Wo = g_W16 + 393216;

    // ---------------- stage 1: inter GEMM ----------------
    float acc[2][8][4];
#pragma unroll
    for (int mt = 0; mt < 2; mt++)
#pragma unroll
        for (int nt = 0; nt < 8; nt++)
#pragma unroll
            for (int r = 0; r < 4; r++) acc[mt][nt][r] = 0.f;

#define ISSUE1(ch) do { \
    const uint32_t _d = (((ch) & 3) * STGH + row * SROWH + half * 8) * 2; \
    const size_t _s = (size_t)row * Mn + (ch) * 16 + half * 8; \
    CPASYNC16(uQ + _d, Aq + _s); \
    CPASYNC16(uS + _d, Bs + _s); \
} while (0)

    ISSUE1(0); CPCOMMIT();
    ISSUE1(1); CPCOMMIT();
    ISSUE1(2); CPCOMMIT();

    for (int ch = 0; ch < 8; ch++) {
        CPWAIT2();
        __syncthreads();
        if (ch + 3 < 8) ISSUE1(ch + 3);
        CPCOMMIT();

        const uint32_t aB = uQ + ((ch & 3) * STGH) * 2;
        const uint32_t bB = uS + ((ch & 3) * STGH) * 2 + boffS;

        uint32_t af[2][4];
        ldsm_x4(af[0], aB + aoffS0);
        ldsm_x4(af[1], aB + aoffS1);
#pragma unroll
        for (int nt = 0; nt < 8; nt++) {
            uint32_t bf[2];
            ldsm_x2(bf, bB + nt * (8 * SROWH * 2));
            mma_f16(acc[0][nt], af[0], bf);
            mma_f16(acc[1][nt], af[1], bf);
        }
    }
#undef ISSUE1

    CPWAIT0();
    __syncthreads();

    // epilogue: att = intra (fp32) + decay^t * inter -> fp16 tile
#pragma unroll
    for (int mt = 0; mt < 2; mt++) {
        const int r0 = wm * 32 + mt * 16 + g;
        const float f0 = powf(DECAYF, (float)r0);
        const float f1 = powf(DECAYF, (float)(r0 + 8));
#pragma unroll
        for (int nt = 0; nt < 8; nt++) {
            const int c0 = wn * 64 + nt * 8 + 2 * t4;
            float2 i0v = *(const float2*)(g_att + base + (size_t)r0 * Mn + c0);
            float2 i1v = *(const float2*)(g_att + base + (size_t)(r0 + 8) * Mn + c0);
            __half2 h0 = __floats2half2_rn(i0v.x + f0 * acc[mt][nt][0],
                                           i0v.y + f0 * acc[mt][nt][1]);
            __half2 h1 = __floats2half2_rn(i1v.x + f1 * acc[mt][nt][2],
                                           i1v.y + f1 * acc[mt][nt][3]);
            *(uint32_t*)(sAtt + r0 * AP + c0)       = *(uint32_t*)&h0;
            *(uint32_t*)(sAtt + (r0 + 8) * AP + c0) = *(uint32_t*)&h1;
        }
    }

#define ISSUE_TILE(cb) do { \
    const uint32_t _bo = ((cb) & 1) * APL; \
    _Pragma("unroll") \
    for (int _it = 0; _it < 8; _it++) { \
        const int _sid = tid + _it * 256; \
        const int _u = _sid >> 4, _sg = _sid & 15; \
        CPASYNC16(uW + (_bo + _u * AP + _sg * 8) * 2, \
                  Wo + (size_t)((cb) * 128 + _u) * Mn + _sg * 8); \
    } \
} while (0)

    ISSUE_TILE(0); CPCOMMIT();
    ISSUE_TILE(1); CPCOMMIT();
    __syncthreads();   // sAtt visible to all warps

    // ---------------- stage 2: y = att x Wo^T + bo ----------------
    const size_t yrow = (size_t)b * Sn + (size_t)c * Cn;

    for (int cb = 0; cb < 8; cb++) {
        CPWAIT1();
        __syncthreads();
        const uint32_t wB = uW + ((cb & 1) * APL) * 2 + boffA;

        float acy[2][8][4];
#pragma unroll
        for (int mt = 0; mt < 2; mt++)
#pragma unroll
            for (int nt = 0; nt < 8; nt++)
#pragma unroll
                for (int r = 0; r < 4; r++) acy[mt][nt][r] = 0.f;

#pragma unroll
        for (int kc = 0; kc < 8; kc++) {
            const uint32_t ko2 = kc * 16 * 2;
            uint32_t af[2][4];
            ldsm_x4(af[0], uAtt + aoffA0 + ko2);
            ldsm_x4(af[1], uAtt + aoffA1 + ko2);
#pragma unroll
            for (int nt = 0; nt < 8; nt++) {
                uint32_t bf[2];
                ldsm_x2(bf, wB + nt * (8 * AP * 2) + ko2);
                mma_f16(acy[0][nt], af[0], bf);
                mma_f16(acy[1][nt], af[1], bf);
            }
        }

#pragma unroll
        for (int mt = 0; mt < 2; mt++) {
            const int r0 = wm * 32 + mt * 16 + g;
#pragma unroll
            for (int nt = 0; nt < 8; nt++) {
                const int c0 = wn * 64 + nt * 8 + 2 * t4;
                const float b0 = bo[cb * 128 + c0], b1 = bo[cb * 128 + c0 + 1];
                *(float2*)(y + (yrow + r0) * Dn + cb * 128 + c0) =
                    make_float2(acy[mt][nt][0] + b0, acy[mt][nt][1] + b1);
                *(float2*)(y + (yrow + r0 + 8) * Dn + cb * 128 + c0) =
                    make_float2(acy[mt][nt][2] + b0, acy[mt][nt][3] + b1);
            }
        }
        __syncthreads();
        if (cb + 2 < 8) { ISSUE_TILE(cb + 2); }
        CPCOMMIT();
    }
#undef ISSUE_TILE
}

// ===========================================================================
// K2: chunk — fp16 hi/lo 2-term compensated (a_hi+a_lo)x b_hi, three 128^3
// GEMMs on resident smem planes, ldmatrix fragments. grid 128, 256 thr.
// ===========================================================================
#define CP 136
#define CPL (128 * CP)

__device__ __forceinline__ void gemm_sm_f16(
    const __half* __restrict__ Ah, const __half* __restrict__ Al,
    const __half* __restrict__ Bh,
    float acc[2][8][4], int wm, int wn, int lane)
{
    const uint32_t uAh = smem_u32(Ah), uAl = smem_u32(Al);
    const uint32_t uBh = smem_u32(Bh);
    const uint32_t aoff0 = ((wm * 32 + AROW_F(lane)) * CP + ACOL_F(lane)) * 2;
    const uint32_t aoff1 = aoff0 + 16 * CP * 2;
    const uint32_t boff  = ((wn * 64 + BROW_F(lane)) * CP + BCOL_F(lane)) * 2;

#pragma unroll
    for (int kk = 0; kk < 8; kk++) {
        const uint32_t ko2 = kk * 16 * 2;
        uint32_t ah[2][4], al[2][4];
        ldsm_x4(ah[0], uAh + aoff0 + ko2);
        ldsm_x4(ah[1], uAh + aoff1 + ko2);
        ldsm_x4(al[0], uAl + aoff0 + ko2);
        ldsm_x4(al[1], uAl + aoff1 + ko2);
#pragma unroll
        for (int nt = 0; nt < 8; nt++) {
            const uint32_t bo2 = boff + nt * (8 * CP * 2) + ko2;
            uint32_t bh[2];
            ldsm_x2(bh, uBh + bo2);
#pragma unroll
            for (int mt = 0; mt < 2; mt++) {
                mma_f16(acc[mt][nt], ah[mt], bh);
                mma_f16(acc[mt][nt], al[mt], bh);
            }
        }
    }
}

__global__ void __launch_bounds__(256) chunk_kernel()
{
    __half* Qh  = (__half*)sm_dyn;      // -> S planes -> Ktw planes
    __half* Ql  = Qh + CPL;
    __half* Kh  = Qh + 2 * CPL;
    __half* Kl  = Qh + 3 * CPL;
    __half* Vth = Qh + 4 * CPL;
    __half* Vtl = Qh + 5 * CPL;
    float* dpow = (float*)(Qh + 6 * CPL);

    const uint32_t uQh = smem_u32(Qh);
    const int tid = threadIdx.x;
    const int lane = tid & 31, wid = tid >> 5;
    const int wm = wid >> 1, wn = wid & 1;
    const int g = lane >> 2, t4 = lane & 3;
    const int b = blockIdx.x / NCn;
    const int c = blockIdx.x % NCn;
    const size_t base = ((size_t)b * Sn + (size_t)c * Cn) * Mn;

#pragma unroll
    for (int it = 0; it < 8; it++) {
        const int sid = tid + it * 256;
        const int u = sid >> 4, seg = sid & 15;
        const uint32_t dof = (u * CP + seg * 8) * 2;
        const size_t sof = base + (size_t)u * Mn + seg * 8;
        CPASYNC16(uQh + dof,               g_qh + sof);
        CPASYNC16(uQh + CPL * 2 + dof,     g_ql + sof);
        CPASYNC16(uQh + 2 * CPL * 2 + dof, g_kh + sof);
        CPASYNC16(uQh + 3 * CPL * 2 + dof, g_kl + sof);
    }
    CPCOMMIT();

    if (tid < 128) dpow[tid] = powf(DECAYF, (float)tid);

#pragma unroll
    for (int it = 0; it < 8; it++) {
        const int task = tid + it * 256;
        const int u = task & 127, i0 = (task >> 7) * 8;
        uint4 dh = *(const uint4*)(g_vh + base + (size_t)u * Mn + i0);
        uint4 dl = *(const uint4*)(g_vl + base + (size_t)u * Mn + i0);
        const __half* ph = (const __half*)&dh;
        const __half* pl = (const __half*)&dl;
#pragma unroll
        for (int j = 0; j < 8; j++) {
            Vth[(i0 + j) * CP + u] = ph[j];
            Vtl[(i0 + j) * CP + u] = pl[j];
        }
    }

    CPWAIT0();
    __syncthreads();

    // GEMM1: S[t][u] = q . k  (A = Q planes, B = K hi)
    float acc[2][8][4];
#pragma unroll
    for (int mt = 0; mt < 2; mt++)
#pragma unroll
        for (int nt = 0; nt < 8; nt++)
#pragma unroll
            for (int r = 0; r < 4; r++) acc[mt][nt][r] = 0.f;
    gemm_sm_f16(Qh, Ql, Kh, acc, wm, wn, lane);

#pragma unroll
    for (int mt = 0; mt < 2; mt++)
#pragma unroll
        for (int nt = 0; nt < 8; nt++)
#pragma unroll
            for (int r = 0; r < 4; r++) {
                const int t = wm * 32 + mt * 16 + g + ((r >= 2) ? 8 : 0);
                const int u = wn * 64 + nt * 8 + 2 * t4 + (r & 1);
                acc[mt][nt][r] = (u < t) ? acc[mt][nt][r] * (LRF * dpow[t - 1 - u]) : 0.f;
            }
    __syncthreads();

#pragma unroll
    for (int mt = 0; mt < 2; mt++) {
        const int r0 = wm * 32 + mt * 16 + g;
#pragma unroll
        for (int nt = 0; nt < 8; nt++) {
            const int c0 = wn * 64 + nt * 8 + 2 * t4;
            __half h0,l0,h1,l1;
            splith(acc[mt][nt][0], h0, l0); splith(acc[mt][nt][1], h1, l1);
            *(uint32_t*)(Qh + r0 * CP + c0) = packh2(h0, h1);
            *(uint32_t*)(Ql + r0 * CP + c0) = packh2(l0, l1);
            splith(acc[mt][nt][2], h0, l0); splith(acc[mt][nt][3], h1, l1);
            *(uint32_t*)(Qh + (r0 + 8) * CP + c0) = packh2(h0, h1);
            *(uint32_t*)(Ql + (r0 + 8) * CP + c0) = packh2(l0, l1);
        }
    }
    __syncthreads();

    // GEMM2: out = S x V^T (A = S planes, B = Vt hi)
    float acc2[2][8][4];
#pragma unroll
    for (int mt = 0; mt < 2; mt++)
#pragma unroll
        for (int nt = 0; nt < 8; nt++)
#pragma unroll
            for (int r = 0; r < 4; r++) acc2[mt][nt][r] = 0.f;
    gemm_sm_f16(Qh, Ql, Vth, acc2, wm, wn, lane);
#pragma unroll
    for (int mt = 0; mt < 2; mt++) {
        const int r0 = wm * 32 + mt * 16 + g;
#pragma unroll
        for (int nt = 0; nt < 8; nt++) {
            const int c0 = wn * 64 + nt * 8 + 2 * t4;
            *(float2*)(g_att + base + (size_t)r0 * Mn + c0)       = make_float2(acc2[mt][nt][0], acc2[mt][nt][1]);
            *(float2*)(g_att + base + (size_t)(r0 + 8) * Mn + c0) = make_float2(acc2[mt][nt][2], acc2[mt][nt][3]);
        }
    }
    __syncthreads();

    // Ktw planes over Q/S area: Ktw[j][u] = k[u][j] * lr*decay^(127-u)
#pragma unroll
    for (int it = 0; it < 8; it++) {
        const int task = tid + it * 256;
        const int u = task & 127, j0 = (task >> 7) * 8;
        const float w = LRF * dpow[127 - u];
#pragma unroll
        for (int j = 0; j < 8; j++) {
            float f = (__half2float(Kh[u * CP + j0 + j]) +
                       __half2float(Kl[u * CP + j0 + j])) * w;
            __half h, l; splith(f, h, l);
            Qh[(j0 + j) * CP + u] = h;
            Ql[(j0 + j) * CP + u] = l;
        }
    }
    __syncthreads();

    // GEMM3: dS = V^T x Ktw (A = Vt planes, B = Ktw hi)
    float acc3[2][8][4];
#pragma unroll
    for (int mt = 0; mt < 2; mt++)
#pragma unroll
        for (int nt = 0; nt < 8; nt++)
#pragma unroll
            for (int r = 0; r < 4; r++) acc3[mt][nt][r] = 0.f;
    gemm_sm_f16(Vth, Vtl, Qh, acc3, wm, wn, lane);

    const size_t dsbase = ((size_t)b * NCn + c) * (Mn * Mn);
#pragma unroll
    for (int mt = 0; mt < 2; mt++) {
        const int r0 = wm * 32 + mt * 16 + g;
#pragma unroll
        for (int nt = 0; nt < 8; nt++) {
            const int c0 = wn * 64 + nt * 8 + 2 * t4;
            *(float2*)(g_dS + dsbase + (size_t)r0 * Mn + c0)       = make_float2(acc3[mt][nt][0], acc3[mt][nt][1]);
            *(float2*)(g_dS + dsbase + (size_t)(r0 + 8) * Mn + c0) = make_float2(acc3[mt][nt][2], acc3[mt][nt][3]);
        }
    }
}

// ===========================================================================
// K3: tile-parallel two-level scan (R10 winner)
// ===========================================================================
__global__ void __launch_bounds__(256) scan_kernel(float* __restrict__ state_out)
{
    __shared__ float t[32][64];
    __shared__ float seg[4][64];
    __shared__ float carr[4][64];

    const int tid = threadIdx.x;
    const int b   = blockIdx.x >> 8;
    const int ij0 = (blockIdx.x & 255) * 64;
    const float dc  = powf(DECAYF, (float)Cn);
    const float dc8 = powf(dc, 8.0f);

#pragma unroll
    for (int it = 0; it < 8; it++) {
        const int idx = tid + it * 256;
        const int cc = idx >> 6, j = idx & 63;
        t[cc][j] = g_dS[((size_t)b * NCn + cc) * 16384 + ij0 + j];
    }
    __syncthreads();

    const int q = tid >> 6, j = tid & 63;

    {
        float r = 0.f;
#pragma unroll
        for (int i = 0; i < 8; i++) r = dc * r + t[q * 8 + i][j];
        seg[q][j] = r;
    }
    __syncthreads();

    if (tid < 64) {
        float csum = 0.f;
#pragma unroll
        for (int qq = 0; qq < 4; qq++) {
            carr[qq][tid] = csum;
            csum = dc8 * csum + seg[qq][tid];
        }
        state_out[(size_t)b * 16384 + ij0 + tid] = csum;
    }
    __syncthreads();

    {
        float r = carr[q][j];
#pragma unroll
        for (int i = 0; i < 8; i++) {
            const int cc = q * 8 + i;
            g_S16[((size_t)b * NCn + cc) * 16384 + ij0 + j] = __float2half_rn(r);
            r = dc * r + t[cc][j];
        }
    }
}

// ===========================================================================
extern "C" void kernel_launch(void* const* d_in, const int* in_sizes, int n_in,
                              void* d_out, int out_size)
{
    const float* x  = (const float*)d_in[0];
    const float* Wk = (const float*)d_in[1];
    const float* bk = (const float*)d_in[2];
    const float* Wv = (const float*)d_in[3];
    const float* bv = (const float*)d_in[4];
    const float* Wq = (const float*)d_in[5];
    const float* bq = (const float*)d_in[6];
    const float* Wo = (const float*)d_in[7];
    const float* bo = (const float*)d_in[8];

    float* y         = (float*)d_out;
    float* state_out = y + (size_t)BSn * Dn;

    const int PROJ_SMEM  = 6 * STGH * 2;                      // 36864
    const int FUSE_SMEM  = (8 * STGH + 3 * APL) * 2;          // 153600
    const int CHUNK_SMEM = 6 * CPL * 2 + 512;                 // 209408

    cudaFuncSetAttribute(proj_kernel,     cudaFuncAttributeMaxDynamicSharedMemorySize, PROJ_SMEM);
    cudaFuncSetAttribute(fuse_out_kernel, cudaFuncAttributeMaxDynamicSharedMemorySize, FUSE_SMEM);
    cudaFuncSetAttribute(chunk_kernel,    cudaFuncAttributeMaxDynamicSharedMemorySize, CHUNK_SMEM);

    conv_w_kernel<<<2048, 256>>>(Wk, Wv, Wq, Wo);
    proj_kernel<<<dim3(BSn / 128, 3), 256, PROJ_SMEM>>>(x, bk, bv, bq);
    chunk_kernel<<<Bn * NCn, 256, CHUNK_SMEM>>>();
    scan_kernel<<<Bn * 256, 256>>>(state_out);
    fuse_out_kernel<<<Bn * NCn, 256, FUSE_SMEM>>>(bo, y);
}